// round 3
// baseline (speedup 1.0000x reference)
#include <cuda_runtime.h>
#include <math.h>

#define Nn 1024
#define Ee 4096
#define NB 64
#define NKB 16   // Nn / NB
#define GPB 120  // persistent grid blocks (<= #SMs, all co-resident)

// ---------------- scratch (static device globals; no allocation) ----------------
__device__ int   d_heads[Ee], d_tails[Ee];
__device__ float d_s[Ee], d_sigma[Ee];
__device__ float d_u[4][Nn];
__device__ float d_r[Nn], d_z[Nn];
__device__ float d_L [Nn * Nn];
__device__ float d_L2[Nn * Nn];
__device__ float d_S [Nn * Nn];
__device__ float d_Ht[(size_t)Ee * Nn];        // H transposed: edge-major [E][N]
__device__ float d_Linv[NKB * NB * NB];        // per-panel inverse of diag Cholesky block
__device__ unsigned g_gen_dev;                 // barrier generation (reset each launch)
__device__ unsigned g_cnt_dev;

// ---------------- fused: extract incidence + zero L + diag setup + copy q ----------------
__global__ void k_extract_init(const float* __restrict__ B, const float* __restrict__ F,
                               const float* __restrict__ Cu, const float* __restrict__ Cx,
                               const float* __restrict__ s0, const float* __restrict__ q) {
    int idx = blockIdx.x * blockDim.x + threadIdx.x;
    if (idx == 0) { g_gen_dev = 0u; g_cnt_dev = 0u; }
    if (idx < Nn * Ee) {
        float v = B[idx];
        int e = idx & (Ee - 1), n = idx >> 12;
        if (v > 0.5f)       d_heads[e] = n;
        else if (v < -0.5f) d_tails[e] = n;
    }
    if (idx < Nn * Nn) d_L[idx] = 0.f;
    if (idx < Ee) {
        size_t d = (size_t)idx * Ee + idx;
        float f = F[d];
        d_s[idx] = f * s0[idx];
        d_sigma[idx] = f * f * Cx[d] + Cu[d];
    }
    if (idx < Nn) d_u[0][idx] = q[idx];
}

__global__ void k_assemble() {
    int e = blockIdx.x * blockDim.x + threadIdx.x;
    if (e >= Ee) return;
    float se = d_s[e];
    int h = d_heads[e], t = d_tails[e];
    atomicAdd(&d_L[h * Nn + h],  se);
    atomicAdd(&d_L[t * Nn + t],  se);
    atomicAdd(&d_L[h * Nn + t], -se);
    atomicAdd(&d_L[t * Nn + h], -se);
}

// d_u[mo] = L * d_u[mi]
__global__ void k_matvec(int mi, int mo) {
    int row = blockIdx.x, t = threadIdx.x;
    const float* Lr = &d_L[(size_t)row * Nn];
    float acc = 0.f;
    for (int j = t; j < Nn; j += 128) acc += Lr[j] * d_u[mi][j];
    for (int off = 16; off; off >>= 1) acc += __shfl_down_sync(0xffffffffu, acc, off);
    __shared__ float ws[4];
    if ((t & 31) == 0) ws[t >> 5] = acc;
    __syncthreads();
    if (t == 0) d_u[mo][row] = ws[0] + ws[1] + ws[2] + ws[3];
}

// ---------------- L2 = L * L^T (symmetric; compute lower, mirror) ----------------
__global__ void k_gemmL2() {
    if (blockIdx.y < blockIdx.x) return;
    __shared__ float As[16][65], Bs[16][65];
    __shared__ float Ts[64][65];
    int I = blockIdx.y * 64, J = blockIdx.x * 64;
    int t = threadIdx.x;
    int lm = t >> 2, lk = (t & 3) << 2;
    int ty = t >> 4, tx = t & 15;
    float acc[4][4] = {};
    for (int k0 = 0; k0 < Nn; k0 += 16) {
        float4 av = *(const float4*)&d_L[(size_t)(I + lm) * Nn + k0 + lk];
        float4 bv = *(const float4*)&d_L[(size_t)(J + lm) * Nn + k0 + lk];
        As[lk + 0][lm] = av.x; As[lk + 1][lm] = av.y; As[lk + 2][lm] = av.z; As[lk + 3][lm] = av.w;
        Bs[lk + 0][lm] = bv.x; Bs[lk + 1][lm] = bv.y; Bs[lk + 2][lm] = bv.z; Bs[lk + 3][lm] = bv.w;
        __syncthreads();
#pragma unroll
        for (int kk = 0; kk < 16; kk++) {
            float ar[4], br[4];
#pragma unroll
            for (int i = 0; i < 4; i++) { ar[i] = As[kk][ty * 4 + i]; br[i] = Bs[kk][tx * 4 + i]; }
#pragma unroll
            for (int i = 0; i < 4; i++)
#pragma unroll
                for (int j = 0; j < 4; j++) acc[i][j] += ar[i] * br[j];
        }
        __syncthreads();
    }
#pragma unroll
    for (int i = 0; i < 4; i++)
#pragma unroll
        for (int j = 0; j < 4; j++)
            d_L2[(size_t)(I + ty * 4 + i) * Nn + J + tx * 4 + j] = acc[i][j];
    if (blockIdx.y != blockIdx.x) {
#pragma unroll
        for (int i = 0; i < 4; i++)
#pragma unroll
            for (int j = 0; j < 4; j++)
                Ts[tx * 4 + j][ty * 4 + i] = acc[i][j];
        __syncthreads();
        for (int idx = t; idx < 64 * 64; idx += 256) {
            int r = idx >> 6, c = idx & 63;
            d_L2[(size_t)(J + r) * Nn + I + c] = Ts[r][c];
        }
    }
}

// ---------------- Ht[e,:] with w computed inline ----------------
__global__ void k_buildHt(const float* __restrict__ a) {
    int e = blockIdx.x;
    int h = d_heads[e], tt = d_tails[e];
    float a1 = a[1], a2 = a[2], a3 = a[3];
    float V0 = d_u[0][h] - d_u[0][tt];
    float V1 = d_u[1][h] - d_u[1][tt];
    float V2 = d_u[2][h] - d_u[2][tt];
    float w0 = a1 * V0 + a2 * V1 + a3 * V2;
    float w1 = a2 * V0 + a3 * V1;
    float w2 = a3 * V0;
    const float* Lh  = &d_L [(size_t)h  * Nn];
    const float* Lt  = &d_L [(size_t)tt * Nn];
    const float* L2h = &d_L2[(size_t)h  * Nn];
    const float* L2t = &d_L2[(size_t)tt * Nn];
    float* out = &d_Ht[(size_t)e * Nn];
    for (int n = threadIdx.x; n < Nn; n += 256) {
        float v = w1 * (Lh[n] - Lt[n]) + w2 * (L2h[n] - L2t[n]);
        if (n == h)  v += w0;
        if (n == tt) v -= w0;
        out[n] = v;
    }
}

// ---------------- S = H diag(sigma) H^T + C_w  (lower tiles only) ----------------
__global__ void k_gemmS(const float* __restrict__ Cw) {
    if (blockIdx.y < blockIdx.x) return;
    __shared__ float As[16][64], Bs[16][64];
    int I = blockIdx.y * 64, J = blockIdx.x * 64;
    int t = threadIdx.x;
    int ldk = t >> 4, ldm = (t & 15) << 2;
    int ty = t >> 4, tx = t & 15;
    float acc[4][4] = {};
    for (int e0 = 0; e0 < Ee; e0 += 16) {
        float sg = d_sigma[e0 + ldk];
        const float* row = &d_Ht[(size_t)(e0 + ldk) * Nn];
        float4 av = *(const float4*)&row[I + ldm];
        float4 bv = *(const float4*)&row[J + ldm];
        av.x *= sg; av.y *= sg; av.z *= sg; av.w *= sg;
        *(float4*)&As[ldk][ldm] = av;
        *(float4*)&Bs[ldk][ldm] = bv;
        __syncthreads();
#pragma unroll
        for (int kk = 0; kk < 16; kk++) {
            float4 a4 = *(const float4*)&As[kk][ty * 4];
            float4 b4 = *(const float4*)&Bs[kk][tx * 4];
            float ar[4] = {a4.x, a4.y, a4.z, a4.w};
            float br[4] = {b4.x, b4.y, b4.z, b4.w};
#pragma unroll
            for (int i = 0; i < 4; i++)
#pragma unroll
                for (int j = 0; j < 4; j++) acc[i][j] += ar[i] * br[j];
        }
        __syncthreads();
    }
#pragma unroll
    for (int i = 0; i < 4; i++)
#pragma unroll
        for (int j = 0; j < 4; j++) {
            size_t idx = (size_t)(I + ty * 4 + i) * Nn + J + tx * 4 + j;
            d_S[idx] = acc[i][j] + Cw[idx];
        }
}

// ================= persistent Cholesky + solve + output =================
__device__ __forceinline__ void gridbar(unsigned target) {
    __syncthreads();
    if (threadIdx.x == 0) {
        __threadfence();
        unsigned v = atomicAdd(&g_cnt_dev, 1u);
        if (v == GPB - 1) {
            atomicExch(&g_cnt_dev, 0u);
            __threadfence();
            atomicExch(&g_gen_dev, target);
        } else {
            while (*((volatile unsigned*)&g_gen_dev) < target) { __nanosleep(64); }
        }
        __threadfence();
    }
    __syncthreads();
}

// 64x64 diag Cholesky + triangular inverse (one block, 256 threads)
__device__ void potrf_dev(int kblk, float (*A)[NB + 1], float (*Bi)[NB + 1]) {
    int o = kblk * NB, t = threadIdx.x;
    __syncthreads();
    for (int idx = t; idx < NB * NB; idx += 256) {
        int r = idx >> 6, c = idx & 63;
        A[r][c] = d_S[(size_t)(o + r) * Nn + o + c];
        Bi[r][c] = (r == c) ? 1.f : 0.f;
    }
    __syncthreads();
    for (int k = 0; k < NB; k++) {
        if (t == 0) A[k][k] = sqrtf(A[k][k]);
        __syncthreads();
        float inv = 1.f / A[k][k];
        if (t < NB) {
            if (t > k) A[t][k] *= inv;
            Bi[k][t] *= inv;
        }
        __syncthreads();
        for (int idx = (k + 1) * NB + t; idx < NB * NB; idx += 256) {
            int r = idx >> 6, c = idx & 63;
            float lrk = A[r][k];
            if (c <= k)          Bi[r][c] -= lrk * Bi[k][c];
            else if (c <= r)     A[r][c]  -= lrk * A[c][k];
        }
        __syncthreads();
    }
    for (int idx = t; idx < NB * NB; idx += 256) {
        int r = idx >> 6, c = idx & 63;
        d_S[(size_t)(o + r) * Nn + o + c] = A[r][c];
        d_Linv[kblk * NB * NB + idx] = Bi[r][c];
    }
    __syncthreads();
}

__device__ void trsm_dev(int kblk, int panel, float (*At)[NB + 1], float (*Lv)[NB + 1]) {
    int o = kblk * NB, t = threadIdx.x;
    int r0 = o + NB + panel * NB;
    __syncthreads();
    for (int idx = t; idx < NB * NB; idx += 256) {
        int r = idx >> 6, c = idx & 63;
        At[r][c] = d_S[(size_t)(r0 + r) * Nn + o + c];
        Lv[r][c] = d_Linv[kblk * NB * NB + idx];
    }
    __syncthreads();
    int ty = t >> 4, tx = t & 15;
    float acc[4][4] = {};
    for (int m = 0; m < NB; m++) {
        float ar[4], br[4];
#pragma unroll
        for (int i = 0; i < 4; i++) { ar[i] = At[ty * 4 + i][m]; br[i] = Lv[tx * 4 + i][m]; }
#pragma unroll
        for (int i = 0; i < 4; i++)
#pragma unroll
            for (int j = 0; j < 4; j++) acc[i][j] += ar[i] * br[j];
    }
    __syncthreads();
#pragma unroll
    for (int i = 0; i < 4; i++)
#pragma unroll
        for (int j = 0; j < 4; j++)
            d_S[(size_t)(r0 + ty * 4 + i) * Nn + o + tx * 4 + j] = acc[i][j];
    __syncthreads();
}

__device__ void syrk_dev(int kblk, int bi, int bj, float (*Pi)[NB + 1], float (*Pj)[NB + 1]) {
    int o = kblk * NB, t = threadIdx.x;
    int ri = o + NB + bi * NB, rj = o + NB + bj * NB;
    __syncthreads();
    for (int idx = t; idx < NB * NB; idx += 256) {
        int r = idx >> 6, c = idx & 63;
        Pi[r][c] = d_S[(size_t)(ri + r) * Nn + o + c];
        Pj[r][c] = d_S[(size_t)(rj + r) * Nn + o + c];
    }
    __syncthreads();
    int ty = t >> 4, tx = t & 15;
    float acc[4][4] = {};
    for (int m = 0; m < NB; m++) {
        float ar[4], br[4];
#pragma unroll
        for (int i = 0; i < 4; i++) { ar[i] = Pi[ty * 4 + i][m]; br[i] = Pj[tx * 4 + i][m]; }
#pragma unroll
        for (int i = 0; i < 4; i++)
#pragma unroll
            for (int j = 0; j < 4; j++) acc[i][j] += ar[i] * br[j];
    }
    __syncthreads();
#pragma unroll
    for (int i = 0; i < 4; i++)
#pragma unroll
        for (int j = 0; j < 4; j++) {
            size_t idx = (size_t)(ri + ty * 4 + i) * Nn + rj + tx * 4 + j;
            d_S[idx] -= acc[i][j];
        }
    __syncthreads();
}

// forward + backward solve by ONE block, using smem-carved vectors
__device__ void solve_dev(float* shAf, float (*shB)[NB + 1]) {
    int t = threadIdx.x, g = t >> 6, i = t & 63;
    float* yv  = shAf;               // 1024
    float* tvv = shAf + 1024;        // 64
    float* part = shAf + 1088;       // 4*64 = 256
    float* zz  = shAf + 1344;        // 1024  (total 2368 <= 4160)
    // ---- forward: L y = r ----
    for (int k = 0; k < NKB; k++) {
        int o = k * NB;
        float acc = 0.f;
        for (int cb = 0; cb < k; cb++) {
            __syncthreads();
            for (int idx = t; idx < NB * NB; idx += 256)
                shB[idx >> 6][idx & 63] = d_S[(size_t)(o + (idx >> 6)) * Nn + cb * NB + (idx & 63)];
            __syncthreads();
            float s = 0.f;
#pragma unroll
            for (int m = 0; m < 16; m++) s += shB[i][g * 16 + m] * yv[cb * NB + g * 16 + m];
            acc += s;
        }
        part[g * 64 + i] = acc;
        __syncthreads();
        if (t < NB) tvv[t] = d_r[o + t] - (part[t] + part[64 + t] + part[128 + t] + part[192 + t]);
        __syncthreads();
        for (int idx = t; idx < NB * NB; idx += 256)
            shB[idx >> 6][idx & 63] = d_Linv[k * NB * NB + idx];
        __syncthreads();
        if (t < NB) {
            float a2 = 0.f;
#pragma unroll
            for (int m = 0; m < NB; m++) a2 += shB[t][m] * tvv[m];
            yv[o + t] = a2;
        }
        __syncthreads();
    }
    // ---- backward: L^T z = y ----
    for (int k = NKB - 1; k >= 0; k--) {
        int o = k * NB;
        float acc = 0.f;
        for (int rb = k + 1; rb < NKB; rb++) {
            __syncthreads();
            for (int idx = t; idx < NB * NB; idx += 256)
                shB[idx >> 6][idx & 63] = d_S[(size_t)(rb * NB + (idx >> 6)) * Nn + o + (idx & 63)];
            __syncthreads();
            float s = 0.f;
#pragma unroll
            for (int m = 0; m < 16; m++) s += shB[g * 16 + m][i] * zz[rb * NB + g * 16 + m];
            acc += s;
        }
        part[g * 64 + i] = acc;
        __syncthreads();
        if (t < NB) tvv[t] = yv[o + t] - (part[t] + part[64 + t] + part[128 + t] + part[192 + t]);
        __syncthreads();
        for (int idx = t; idx < NB * NB; idx += 256)
            shB[idx >> 6][idx & 63] = d_Linv[k * NB * NB + idx];
        __syncthreads();
        if (t < NB) {
            float a2 = 0.f;
#pragma unroll
            for (int m = 0; m < NB; m++) a2 += shB[m][t] * tvv[m];
            zz[o + t] = a2;
        }
        __syncthreads();
    }
    for (int n = t; n < Nn; n += 256) d_z[n] = zz[n];
}

__global__ void __launch_bounds__(256, 1)
k_chol_all(const float* __restrict__ a, const float* __restrict__ y, float* __restrict__ out) {
    __shared__ float shA[NB][NB + 1];
    __shared__ float shB[NB][NB + 1];
    int bid = blockIdx.x, t = threadIdx.x;
    unsigned gen = 0;

    // phase 0: potrf(0) on block 0; residual r on last block
    if (bid == 0) {
        potrf_dev(0, shA, shB);
    } else if (bid == GPB - 1) {
        float a0 = a[0], a1 = a[1], a2 = a[2], a3 = a[3];
        for (int n = t; n < Nn; n += 256)
            d_r[n] = y[n] - (a0 * d_u[0][n] + a1 * d_u[1][n] + a2 * d_u[2][n] + a3 * d_u[3][n]);
    }
    gridbar(++gen);

    for (int k = 0; k < NKB - 1; k++) {
        int rb = NKB - 1 - k;
        if (bid < rb) trsm_dev(k, bid, shA, shB);
        gridbar(++gen);
        int T = rb * (rb + 1) / 2;
        for (int tt = bid; tt < T; tt += GPB) {
            int bi = (int)((sqrtf(8.f * tt + 1.f) - 1.f) * 0.5f);
            while ((bi + 1) * (bi + 2) / 2 <= tt) bi++;
            while (bi * (bi + 1) / 2 > tt) bi--;
            int bj = tt - bi * (bi + 1) / 2;
            syrk_dev(k, bi, bj, shA, shB);
        }
        if (bid == 0) potrf_dev(k + 1, shA, shB);   // lookahead: hidden under syrk
        gridbar(++gen);
    }

    if (bid == 0) solve_dev(&shA[0][0], shB);
    gridbar(++gen);

    // output: out[e] = relu(s[e] + sigma[e] * dot(Ht[e,:], z))
    int w = t >> 5, lane = t & 31;
    for (int e = bid * 8 + w; e < Ee; e += GPB * 8) {
        const float* row = &d_Ht[(size_t)e * Nn];
        float acc = 0.f;
        for (int n = lane; n < Nn; n += 32) acc += row[n] * d_z[n];
        for (int off = 16; off; off >>= 1) acc += __shfl_down_sync(0xffffffffu, acc, off);
        if (lane == 0) out[e] = fmaxf(d_s[e] + d_sigma[e] * acc, 0.f);
    }
}

// ---------------- launch ----------------
extern "C" void kernel_launch(void* const* d_in, const int* in_sizes, int n_in,
                              void* d_out, int out_size) {
    (void)in_sizes; (void)n_in; (void)out_size;
    const float* F  = (const float*)d_in[0];
    const float* B  = (const float*)d_in[1];
    const float* Cu = (const float*)d_in[2];
    const float* Cw = (const float*)d_in[3];
    const float* Cx = (const float*)d_in[4];
    const float* s0 = (const float*)d_in[5];
    const float* a  = (const float*)d_in[6];
    const float* q  = (const float*)d_in[7];
    const float* y  = (const float*)d_in[8];
    float* out = (float*)d_out;

    k_extract_init<<<(Nn * Ee + 255) / 256, 256>>>(B, F, Cu, Cx, s0, q);
    k_assemble<<<(Ee + 255) / 256, 256>>>();
    k_matvec<<<Nn, 128>>>(0, 1);
    k_matvec<<<Nn, 128>>>(1, 2);
    k_matvec<<<Nn, 128>>>(2, 3);
    k_gemmL2<<<dim3(16, 16), 256>>>();
    k_buildHt<<<Ee, 256>>>(a);
    k_gemmS<<<dim3(16, 16), 256>>>(Cw);
    k_chol_all<<<GPB, 256>>>(a, y, out);
}

// round 4
// speedup vs baseline: 1.1310x; 1.1310x over previous
#include <cuda_runtime.h>
#include <math.h>

#define Nn 1024
#define Ee 4096
#define NB 64
#define NKB 16   // Nn / NB
#define GPB 120  // persistent grid blocks (<= #SMs, all co-resident)

// ---------------- scratch (static device globals; no allocation) ----------------
__device__ int   d_heads[Ee], d_tails[Ee];
__device__ float d_s[Ee], d_sigma[Ee];
__device__ float d_u[4][Nn];
__device__ float d_r[Nn], d_z[Nn];
__device__ float d_L [Nn * Nn];
__device__ float d_L2[Nn * Nn];
__device__ float d_S [Nn * Nn];
__device__ float d_U [Nn * Nn];                // transposed lower panels (for backward solve)
__device__ float d_Ht[(size_t)Ee * Nn];        // H transposed: edge-major [E][N]
__device__ float d_Linv[NKB * NB * NB];        // per-panel inverse of diag Cholesky block
__device__ unsigned g_gen_dev[2];              // barrier generation (reset each launch)
__device__ unsigned g_cnt_dev[2];

// ---------------- fused: extract incidence + zero L + diag setup + copy q ----------------
__global__ void k_extract_init(const float* __restrict__ B, const float* __restrict__ F,
                               const float* __restrict__ Cu, const float* __restrict__ Cx,
                               const float* __restrict__ s0, const float* __restrict__ q) {
    int idx = blockIdx.x * blockDim.x + threadIdx.x;
    if (idx < 2) { g_gen_dev[idx] = 0u; g_cnt_dev[idx] = 0u; }
    if (idx < Nn * Ee) {
        float v = B[idx];
        int e = idx & (Ee - 1), n = idx >> 12;
        if (v > 0.5f)       d_heads[e] = n;
        else if (v < -0.5f) d_tails[e] = n;
    }
    if (idx < Nn * Nn) d_L[idx] = 0.f;
    if (idx < Ee) {
        size_t d = (size_t)idx * Ee + idx;
        float f = F[d];
        d_s[idx] = f * s0[idx];
        d_sigma[idx] = f * f * Cx[d] + Cu[d];
    }
    if (idx < Nn) d_u[0][idx] = q[idx];
}

// ================= grid barrier =================
__device__ __forceinline__ void gridbar(int which, unsigned target) {
    __syncthreads();
    if (threadIdx.x == 0) {
        __threadfence();
        unsigned v = atomicAdd(&g_cnt_dev[which], 1u);
        if (v == GPB - 1) {
            atomicExch(&g_cnt_dev[which], 0u);
            __threadfence();
            atomicExch(&g_gen_dev[which], target);
        } else {
            while (*((volatile unsigned*)&g_gen_dev[which]) < target) { __nanosleep(64); }
        }
        __threadfence();
    }
    __syncthreads();
}

// ---------------- persistent front: assemble + 3 matvecs ----------------
__global__ void __launch_bounds__(256, 1) k_front() {
    int bid = blockIdx.x, t = threadIdx.x;
    __shared__ float ws[8];
    unsigned gen = 0;
    // assemble
    for (int e = bid * 256 + t; e < Ee; e += GPB * 256) {
        float se = d_s[e];
        int h = d_heads[e], tl = d_tails[e];
        atomicAdd(&d_L[h * Nn + h],  se);
        atomicAdd(&d_L[tl * Nn + tl],  se);
        atomicAdd(&d_L[h * Nn + tl], -se);
        atomicAdd(&d_L[tl * Nn + h], -se);
    }
    gridbar(0, ++gen);
    // three dependent matvecs
    for (int m = 0; m < 3; m++) {
        for (int row = bid; row < Nn; row += GPB) {
            float4 lv = *(const float4*)&d_L[(size_t)row * Nn + t * 4];
            float4 uv = *(const float4*)&d_u[m][t * 4];
            float acc = lv.x * uv.x + lv.y * uv.y + lv.z * uv.z + lv.w * uv.w;
            for (int off = 16; off; off >>= 1) acc += __shfl_down_sync(0xffffffffu, acc, off);
            if ((t & 31) == 0) ws[t >> 5] = acc;
            __syncthreads();
            if (t == 0) {
                float s = 0.f;
#pragma unroll
                for (int w = 0; w < 8; w++) s += ws[w];
                d_u[m + 1][row] = s;
            }
            __syncthreads();
        }
        gridbar(0, ++gen);
    }
}

// ---------------- L2 = L * L^T (symmetric; compute lower, mirror; prefetched) ----------------
__global__ void k_gemmL2() {
    if (blockIdx.y < blockIdx.x) return;
    __shared__ float As[16][65], Bs[16][65];
    __shared__ float Ts[64][65];
    int I = blockIdx.y * 64, J = blockIdx.x * 64;
    int t = threadIdx.x;
    int lm = t >> 2, lk = (t & 3) << 2;
    int ty = t >> 4, tx = t & 15;
    float acc[4][4] = {};
    float4 av = *(const float4*)&d_L[(size_t)(I + lm) * Nn + lk];
    float4 bv = *(const float4*)&d_L[(size_t)(J + lm) * Nn + lk];
    As[lk + 0][lm] = av.x; As[lk + 1][lm] = av.y; As[lk + 2][lm] = av.z; As[lk + 3][lm] = av.w;
    Bs[lk + 0][lm] = bv.x; Bs[lk + 1][lm] = bv.y; Bs[lk + 2][lm] = bv.z; Bs[lk + 3][lm] = bv.w;
    for (int k0 = 0; k0 < Nn; k0 += 16) {
        __syncthreads();
        bool has = (k0 + 16 < Nn);
        float4 an, bn;
        if (has) {
            an = *(const float4*)&d_L[(size_t)(I + lm) * Nn + k0 + 16 + lk];
            bn = *(const float4*)&d_L[(size_t)(J + lm) * Nn + k0 + 16 + lk];
        }
#pragma unroll
        for (int kk = 0; kk < 16; kk++) {
            float ar[4], br[4];
#pragma unroll
            for (int i = 0; i < 4; i++) { ar[i] = As[kk][ty * 4 + i]; br[i] = Bs[kk][tx * 4 + i]; }
#pragma unroll
            for (int i = 0; i < 4; i++)
#pragma unroll
                for (int j = 0; j < 4; j++) acc[i][j] += ar[i] * br[j];
        }
        __syncthreads();
        if (has) {
            As[lk + 0][lm] = an.x; As[lk + 1][lm] = an.y; As[lk + 2][lm] = an.z; As[lk + 3][lm] = an.w;
            Bs[lk + 0][lm] = bn.x; Bs[lk + 1][lm] = bn.y; Bs[lk + 2][lm] = bn.z; Bs[lk + 3][lm] = bn.w;
        }
    }
#pragma unroll
    for (int i = 0; i < 4; i++)
#pragma unroll
        for (int j = 0; j < 4; j++)
            d_L2[(size_t)(I + ty * 4 + i) * Nn + J + tx * 4 + j] = acc[i][j];
    if (blockIdx.y != blockIdx.x) {
#pragma unroll
        for (int i = 0; i < 4; i++)
#pragma unroll
            for (int j = 0; j < 4; j++)
                Ts[tx * 4 + j][ty * 4 + i] = acc[i][j];
        __syncthreads();
        for (int idx = t; idx < 64 * 64; idx += 256) {
            int r = idx >> 6, c = idx & 63;
            d_L2[(size_t)(J + r) * Nn + I + c] = Ts[r][c];
        }
    }
}

// ---------------- Ht[e,:] with w computed inline ----------------
__global__ void k_buildHt(const float* __restrict__ a) {
    int e = blockIdx.x;
    int h = d_heads[e], tt = d_tails[e];
    float a1 = a[1], a2 = a[2], a3 = a[3];
    float V0 = d_u[0][h] - d_u[0][tt];
    float V1 = d_u[1][h] - d_u[1][tt];
    float V2 = d_u[2][h] - d_u[2][tt];
    float w0 = a1 * V0 + a2 * V1 + a3 * V2;
    float w1 = a2 * V0 + a3 * V1;
    float w2 = a3 * V0;
    const float* Lh  = &d_L [(size_t)h  * Nn];
    const float* Lt  = &d_L [(size_t)tt * Nn];
    const float* L2h = &d_L2[(size_t)h  * Nn];
    const float* L2t = &d_L2[(size_t)tt * Nn];
    float* out = &d_Ht[(size_t)e * Nn];
    for (int n = threadIdx.x; n < Nn; n += 256) {
        float v = w1 * (Lh[n] - Lt[n]) + w2 * (L2h[n] - L2t[n]);
        if (n == h)  v += w0;
        if (n == tt) v -= w0;
        out[n] = v;
    }
}

// ---------------- S = H diag(sigma) H^T + C_w  (lower tiles only; prefetched) ----------------
__global__ void k_gemmS(const float* __restrict__ Cw) {
    if (blockIdx.y < blockIdx.x) return;
    __shared__ float As[16][64], Bs[16][64];
    int I = blockIdx.y * 64, J = blockIdx.x * 64;
    int t = threadIdx.x;
    int ldk = t >> 4, ldm = (t & 15) << 2;
    int ty = t >> 4, tx = t & 15;
    float acc[4][4] = {};
    {
        float sg = d_sigma[ldk];
        const float* row = &d_Ht[(size_t)ldk * Nn];
        float4 av = *(const float4*)&row[I + ldm];
        float4 bv = *(const float4*)&row[J + ldm];
        av.x *= sg; av.y *= sg; av.z *= sg; av.w *= sg;
        *(float4*)&As[ldk][ldm] = av;
        *(float4*)&Bs[ldk][ldm] = bv;
    }
    for (int e0 = 0; e0 < Ee; e0 += 16) {
        __syncthreads();
        bool has = (e0 + 16 < Ee);
        float4 an, bn; float sgn = 0.f;
        if (has) {
            sgn = d_sigma[e0 + 16 + ldk];
            const float* row = &d_Ht[(size_t)(e0 + 16 + ldk) * Nn];
            an = *(const float4*)&row[I + ldm];
            bn = *(const float4*)&row[J + ldm];
        }
#pragma unroll
        for (int kk = 0; kk < 16; kk++) {
            float4 a4 = *(const float4*)&As[kk][ty * 4];
            float4 b4 = *(const float4*)&Bs[kk][tx * 4];
            float ar[4] = {a4.x, a4.y, a4.z, a4.w};
            float br[4] = {b4.x, b4.y, b4.z, b4.w};
#pragma unroll
            for (int i = 0; i < 4; i++)
#pragma unroll
                for (int j = 0; j < 4; j++) acc[i][j] += ar[i] * br[j];
        }
        __syncthreads();
        if (has) {
            an.x *= sgn; an.y *= sgn; an.z *= sgn; an.w *= sgn;
            *(float4*)&As[ldk][ldm] = an;
            *(float4*)&Bs[ldk][ldm] = bn;
        }
    }
#pragma unroll
    for (int i = 0; i < 4; i++)
#pragma unroll
        for (int j = 0; j < 4; j++) {
            size_t idx = (size_t)(I + ty * 4 + i) * Nn + J + tx * 4 + j;
            d_S[idx] = acc[i][j] + Cw[idx];
        }
}

// ================= persistent Cholesky + solve + output =================

// 64x64 diag Cholesky + triangular inverse (one block, 256 threads)
__device__ void potrf_dev(int kblk, float (*A)[NB + 1], float (*Bi)[NB + 1]) {
    int o = kblk * NB, t = threadIdx.x;
    __syncthreads();
    for (int idx = t; idx < NB * NB; idx += 256) {
        int r = idx >> 6, c = idx & 63;
        A[r][c] = d_S[(size_t)(o + r) * Nn + o + c];
        Bi[r][c] = (r == c) ? 1.f : 0.f;
    }
    __syncthreads();
    for (int k = 0; k < NB; k++) {
        if (t == 0) A[k][k] = sqrtf(A[k][k]);
        __syncthreads();
        float inv = 1.f / A[k][k];
        if (t < NB) {
            if (t > k) A[t][k] *= inv;
            Bi[k][t] *= inv;
        }
        __syncthreads();
        for (int idx = (k + 1) * NB + t; idx < NB * NB; idx += 256) {
            int r = idx >> 6, c = idx & 63;
            float lrk = A[r][k];
            if (c <= k)          Bi[r][c] -= lrk * Bi[k][c];
            else if (c <= r)     A[r][c]  -= lrk * A[c][k];
        }
        __syncthreads();
    }
    for (int idx = t; idx < NB * NB; idx += 256) {
        int r = idx >> 6, c = idx & 63;
        d_S[(size_t)(o + r) * Nn + o + c] = A[r][c];
        d_Linv[kblk * NB * NB + idx] = Bi[r][c];
    }
    __syncthreads();
}

__device__ void trsm_dev(int kblk, int panel, float (*At)[NB + 1], float (*Lv)[NB + 1]) {
    int o = kblk * NB, t = threadIdx.x;
    int r0 = o + NB + panel * NB;
    __syncthreads();
    for (int idx = t; idx < NB * NB; idx += 256) {
        int r = idx >> 6, c = idx & 63;
        At[r][c] = d_S[(size_t)(r0 + r) * Nn + o + c];
        Lv[r][c] = d_Linv[kblk * NB * NB + idx];
    }
    __syncthreads();
    int ty = t >> 4, tx = t & 15;
    float acc[4][4] = {};
    for (int m = 0; m < NB; m++) {
        float ar[4], br[4];
#pragma unroll
        for (int i = 0; i < 4; i++) { ar[i] = At[ty * 4 + i][m]; br[i] = Lv[tx * 4 + i][m]; }
#pragma unroll
        for (int i = 0; i < 4; i++)
#pragma unroll
            for (int j = 0; j < 4; j++) acc[i][j] += ar[i] * br[j];
    }
    __syncthreads();
#pragma unroll
    for (int i = 0; i < 4; i++)
#pragma unroll
        for (int j = 0; j < 4; j++) {
            d_S[(size_t)(r0 + ty * 4 + i) * Nn + o + tx * 4 + j] = acc[i][j];
            Lv[tx * 4 + j][ty * 4 + i] = acc[i][j];   // transpose for d_U
        }
    __syncthreads();
    for (int idx = t; idx < NB * NB; idx += 256) {
        int r = idx >> 6, c = idx & 63;
        d_U[(size_t)(o + r) * Nn + r0 + c] = Lv[r][c];
    }
    __syncthreads();
}

__device__ void syrk_dev(int kblk, int bi, int bj, float (*Pi)[NB + 1], float (*Pj)[NB + 1]) {
    int o = kblk * NB, t = threadIdx.x;
    int ri = o + NB + bi * NB, rj = o + NB + bj * NB;
    __syncthreads();
    for (int idx = t; idx < NB * NB; idx += 256) {
        int r = idx >> 6, c = idx & 63;
        Pi[r][c] = d_S[(size_t)(ri + r) * Nn + o + c];
        Pj[r][c] = d_S[(size_t)(rj + r) * Nn + o + c];
    }
    __syncthreads();
    int ty = t >> 4, tx = t & 15;
    float acc[4][4] = {};
    for (int m = 0; m < NB; m++) {
        float ar[4], br[4];
#pragma unroll
        for (int i = 0; i < 4; i++) { ar[i] = Pi[ty * 4 + i][m]; br[i] = Pj[tx * 4 + i][m]; }
#pragma unroll
        for (int i = 0; i < 4; i++)
#pragma unroll
            for (int j = 0; j < 4; j++) acc[i][j] += ar[i] * br[j];
    }
    __syncthreads();
#pragma unroll
    for (int i = 0; i < 4; i++)
#pragma unroll
        for (int j = 0; j < 4; j++) {
            size_t idx = (size_t)(ri + ty * 4 + i) * Nn + rj + tx * 4 + j;
            d_S[idx] -= acc[i][j];
        }
    __syncthreads();
}

// forward + backward solve by ONE block (256 threads), direct global loads
__device__ void solve_dev(float* sh, float (*shB)[NB + 1]) {
    int t = threadIdx.x;
    int r = t >> 2, q = t & 3;           // 4 threads per row/col
    float* yv   = sh;                    // 1024
    float* zz   = sh + 1024;             // 1024
    float* part = sh + 2048;             // 64
    float* tvv  = sh + 2112;             // 64
    // ---- forward: L y = r ----
    for (int k = 0; k < NKB; k++) {
        int o = k * NB;
        float acc = 0.f;
        const float* Srow = &d_S[(size_t)(o + r) * Nn + q * 16];
        for (int cb = 0; cb < k; cb++) {
#pragma unroll
            for (int m = 0; m < 4; m++) {
                float4 v = *(const float4*)&Srow[cb * 64 + m * 4];
                int j = cb * 64 + q * 16 + m * 4;
                acc += v.x * yv[j] + v.y * yv[j + 1] + v.z * yv[j + 2] + v.w * yv[j + 3];
            }
        }
        acc += __shfl_xor_sync(0xffffffffu, acc, 1);
        acc += __shfl_xor_sync(0xffffffffu, acc, 2);
        if (q == 0) part[r] = acc;
        // stage Linv tile
        for (int idx = t; idx < NB * NB; idx += 256)
            shB[idx >> 6][idx & 63] = d_Linv[k * NB * NB + idx];
        __syncthreads();
        if (t < NB) tvv[t] = d_r[o + t] - part[t];
        __syncthreads();
        if (t < NB) {
            float a2 = 0.f;
#pragma unroll
            for (int m = 0; m < NB; m++) a2 += shB[t][m] * tvv[m];
            yv[o + t] = a2;
        }
        __syncthreads();
    }
    // ---- backward: L^T z = y  (reads d_U rows, coalesced) ----
    for (int k = NKB - 1; k >= 0; k--) {
        int o = k * NB;
        float acc = 0.f;
        const float* Urow = &d_U[(size_t)(o + r) * Nn + q * 16];
        for (int rb = k + 1; rb < NKB; rb++) {
#pragma unroll
            for (int m = 0; m < 4; m++) {
                float4 v = *(const float4*)&Urow[rb * 64 + m * 4];
                int j = rb * 64 + q * 16 + m * 4;
                acc += v.x * zz[j] + v.y * zz[j + 1] + v.z * zz[j + 2] + v.w * zz[j + 3];
            }
        }
        acc += __shfl_xor_sync(0xffffffffu, acc, 1);
        acc += __shfl_xor_sync(0xffffffffu, acc, 2);
        if (q == 0) part[r] = acc;
        for (int idx = t; idx < NB * NB; idx += 256)
            shB[idx >> 6][idx & 63] = d_Linv[k * NB * NB + idx];
        __syncthreads();
        if (t < NB) tvv[t] = yv[o + t] - part[t];
        __syncthreads();
        if (t < NB) {
            float a2 = 0.f;
#pragma unroll
            for (int m = 0; m < NB; m++) a2 += shB[m][t] * tvv[m];
            zz[o + t] = a2;
        }
        __syncthreads();
    }
    for (int n = t; n < Nn; n += 256) d_z[n] = zz[n];
}

__global__ void __launch_bounds__(256, 1)
k_chol_all(const float* __restrict__ a, const float* __restrict__ y, float* __restrict__ out) {
    __shared__ float shA[NB][NB + 1];
    __shared__ float shB[NB][NB + 1];
    int bid = blockIdx.x, t = threadIdx.x;
    unsigned gen = 0;

    // phase 0: potrf(0) on block 0; residual r on last block
    if (bid == 0) {
        potrf_dev(0, shA, shB);
    } else if (bid == GPB - 1) {
        float a0 = a[0], a1 = a[1], a2 = a[2], a3 = a[3];
        for (int n = t; n < Nn; n += 256)
            d_r[n] = y[n] - (a0 * d_u[0][n] + a1 * d_u[1][n] + a2 * d_u[2][n] + a3 * d_u[3][n]);
    }
    gridbar(1, ++gen);

    for (int k = 0; k < NKB - 1; k++) {
        int rb = NKB - 1 - k;
        if (bid < rb) trsm_dev(k, bid, shA, shB);
        gridbar(1, ++gen);
        int T = rb * (rb + 1) / 2;
        for (int tt = bid; tt < T; tt += GPB) {
            int bi = (int)((sqrtf(8.f * tt + 1.f) - 1.f) * 0.5f);
            while ((bi + 1) * (bi + 2) / 2 <= tt) bi++;
            while (bi * (bi + 1) / 2 > tt) bi--;
            int bj = tt - bi * (bi + 1) / 2;
            syrk_dev(k, bi, bj, shA, shB);
        }
        if (bid == 0) potrf_dev(k + 1, shA, shB);   // lookahead after own tile(0,0)
        gridbar(1, ++gen);
    }

    if (bid == 0) solve_dev(&shA[0][0], shB);
    gridbar(1, ++gen);

    // output: out[e] = relu(s[e] + sigma[e] * dot(Ht[e,:], z))
    int w = t >> 5, lane = t & 31;
    for (int e = bid * 8 + w; e < Ee; e += GPB * 8) {
        const float* row = &d_Ht[(size_t)e * Nn];
        float acc = 0.f;
        for (int n = lane; n < Nn; n += 32) acc += row[n] * d_z[n];
        for (int off = 16; off; off >>= 1) acc += __shfl_down_sync(0xffffffffu, acc, off);
        if (lane == 0) out[e] = fmaxf(d_s[e] + d_sigma[e] * acc, 0.f);
    }
}

// ---------------- launch ----------------
extern "C" void kernel_launch(void* const* d_in, const int* in_sizes, int n_in,
                              void* d_out, int out_size) {
    (void)in_sizes; (void)n_in; (void)out_size;
    const float* F  = (const float*)d_in[0];
    const float* B  = (const float*)d_in[1];
    const float* Cu = (const float*)d_in[2];
    const float* Cw = (const float*)d_in[3];
    const float* Cx = (const float*)d_in[4];
    const float* s0 = (const float*)d_in[5];
    const float* a  = (const float*)d_in[6];
    const float* q  = (const float*)d_in[7];
    const float* y  = (const float*)d_in[8];
    float* out = (float*)d_out;

    k_extract_init<<<(Nn * Ee + 255) / 256, 256>>>(B, F, Cu, Cx, s0, q);   // #1
    k_front<<<GPB, 256>>>();                                               // #2
    k_gemmL2<<<dim3(16, 16), 256>>>();                                     // #3
    k_buildHt<<<Ee, 256>>>(a);                                             // #4
    k_gemmS<<<dim3(16, 16), 256>>>(Cw);                                    // #5  <- ncu capture slot
    k_chol_all<<<GPB, 256>>>(a, y, out);                                   // #6
}

// round 5
// speedup vs baseline: 1.1491x; 1.0161x over previous
#include <cuda_runtime.h>
#include <math.h>

#define Nn 1024
#define Ee 4096
#define NB 64
#define NKB 16   // Nn / NB
#define GPB 120  // persistent grid blocks (<= #SMs, all co-resident)

// ---------------- scratch (static device globals; no allocation) ----------------
__device__ int   d_heads[Ee], d_tails[Ee];
__device__ float d_s[Ee], d_sigma[Ee];
__device__ float d_u[4][Nn];
__device__ float d_r[Nn], d_z[Nn], d_v1[Nn], d_v2[Nn];
__device__ float d_L [Nn * Nn];
__device__ float d_L2[Nn * Nn];
__device__ float d_S [Nn * Nn];
__device__ float d_U [Nn * Nn];                // transposed lower panels (backward solve)
__device__ float d_Ht[(size_t)Ee * Nn];        // H transposed: edge-major [E][N]
__device__ float d_Linv[NKB * NB * NB];        // per-panel inverse of diag Cholesky block
__device__ unsigned g_gen_dev[2];              // 0: front, 1: chol
__device__ unsigned g_cnt_dev[2];

// ================= grid barrier (pure spin) =================
__device__ __forceinline__ void gridbar(int which, unsigned target) {
    __syncthreads();
    if (threadIdx.x == 0) {
        __threadfence();
        unsigned v = atomicAdd(&g_cnt_dev[which], 1u);
        if (v == GPB - 1) {
            atomicExch(&g_cnt_dev[which], 0u);
            __threadfence();
            atomicExch(&g_gen_dev[which], target);
        } else {
            while (*(volatile unsigned*)&g_gen_dev[which] < target) { }
        }
        __threadfence();
    }
    __syncthreads();
}

// ---------------- persistent front: extract + init + assemble + 3 matvecs ----------------
__global__ void __launch_bounds__(256, 1)
k_front(const float* __restrict__ B, const float* __restrict__ F,
        const float* __restrict__ Cu, const float* __restrict__ Cx,
        const float* __restrict__ s0, const float* __restrict__ q) {
    int bid = blockIdx.x, t = threadIdx.x;
    __shared__ float ws[8];
    unsigned gen = 0;
    // phase A: extract incidence, zero L, diag setup, copy q
    for (int idx = bid * 256 + t; idx < Nn * Ee; idx += GPB * 256) {
        float v = B[idx];
        int e = idx & (Ee - 1), n = idx >> 12;
        if (v > 0.5f)       d_heads[e] = n;
        else if (v < -0.5f) d_tails[e] = n;
        if (idx < Nn * Nn) d_L[idx] = 0.f;
        if (idx < Ee) {
            size_t d = (size_t)idx * Ee + idx;
            float f = F[d];
            d_s[idx] = f * s0[idx];
            d_sigma[idx] = f * f * Cx[d] + Cu[d];
        }
        if (idx < Nn) d_u[0][idx] = q[idx];
    }
    gridbar(0, ++gen);
    // phase B: assemble Laplacian
    for (int e = bid * 256 + t; e < Ee; e += GPB * 256) {
        float se = d_s[e];
        int h = d_heads[e], tl = d_tails[e];
        atomicAdd(&d_L[h * Nn + h],  se);
        atomicAdd(&d_L[tl * Nn + tl],  se);
        atomicAdd(&d_L[h * Nn + tl], -se);
        atomicAdd(&d_L[tl * Nn + h], -se);
    }
    gridbar(0, ++gen);
    // phase C: u_{m+1} = L u_m, three times
    for (int m = 0; m < 3; m++) {
        for (int row = bid; row < Nn; row += GPB) {
            float4 lv = *(const float4*)&d_L[(size_t)row * Nn + t * 4];
            float4 uv = *(const float4*)&d_u[m][t * 4];
            float acc = lv.x * uv.x + lv.y * uv.y + lv.z * uv.z + lv.w * uv.w;
            for (int off = 16; off; off >>= 1) acc += __shfl_down_sync(0xffffffffu, acc, off);
            if ((t & 31) == 0) ws[t >> 5] = acc;
            __syncthreads();
            if (t == 0) {
                float s = 0.f;
#pragma unroll
                for (int w = 0; w < 8; w++) s += ws[w];
                d_u[m + 1][row] = s;
            }
            __syncthreads();
        }
        gridbar(0, ++gen);
    }
}

// ---------------- L2 = L * L^T (symmetric; compute lower, mirror; prefetched) ----------------
__global__ void k_gemmL2() {
    if (blockIdx.x == 0 && blockIdx.y == 0 && threadIdx.x == 0) {
        g_gen_dev[1] = 0u; g_cnt_dev[1] = 0u;   // reset chol barrier for this replay
    }
    if (blockIdx.y < blockIdx.x) return;
    __shared__ float As[16][65], Bs[16][65];
    __shared__ float Ts[64][65];
    int I = blockIdx.y * 64, J = blockIdx.x * 64;
    int t = threadIdx.x;
    int lm = t >> 2, lk = (t & 3) << 2;
    int ty = t >> 4, tx = t & 15;
    float acc[4][4] = {};
    float4 av = *(const float4*)&d_L[(size_t)(I + lm) * Nn + lk];
    float4 bv = *(const float4*)&d_L[(size_t)(J + lm) * Nn + lk];
    As[lk + 0][lm] = av.x; As[lk + 1][lm] = av.y; As[lk + 2][lm] = av.z; As[lk + 3][lm] = av.w;
    Bs[lk + 0][lm] = bv.x; Bs[lk + 1][lm] = bv.y; Bs[lk + 2][lm] = bv.z; Bs[lk + 3][lm] = bv.w;
    for (int k0 = 0; k0 < Nn; k0 += 16) {
        __syncthreads();
        bool has = (k0 + 16 < Nn);
        float4 an, bn;
        if (has) {
            an = *(const float4*)&d_L[(size_t)(I + lm) * Nn + k0 + 16 + lk];
            bn = *(const float4*)&d_L[(size_t)(J + lm) * Nn + k0 + 16 + lk];
        }
#pragma unroll
        for (int kk = 0; kk < 16; kk++) {
            float ar[4], br[4];
#pragma unroll
            for (int i = 0; i < 4; i++) { ar[i] = As[kk][ty * 4 + i]; br[i] = Bs[kk][tx * 4 + i]; }
#pragma unroll
            for (int i = 0; i < 4; i++)
#pragma unroll
                for (int j = 0; j < 4; j++) acc[i][j] += ar[i] * br[j];
        }
        __syncthreads();
        if (has) {
            As[lk + 0][lm] = an.x; As[lk + 1][lm] = an.y; As[lk + 2][lm] = an.z; As[lk + 3][lm] = an.w;
            Bs[lk + 0][lm] = bn.x; Bs[lk + 1][lm] = bn.y; Bs[lk + 2][lm] = bn.z; Bs[lk + 3][lm] = bn.w;
        }
    }
#pragma unroll
    for (int i = 0; i < 4; i++)
#pragma unroll
        for (int j = 0; j < 4; j++)
            d_L2[(size_t)(I + ty * 4 + i) * Nn + J + tx * 4 + j] = acc[i][j];
    if (blockIdx.y != blockIdx.x) {
#pragma unroll
        for (int i = 0; i < 4; i++)
#pragma unroll
            for (int j = 0; j < 4; j++)
                Ts[tx * 4 + j][ty * 4 + i] = acc[i][j];
        __syncthreads();
        for (int idx = t; idx < 64 * 64; idx += 256) {
            int r = idx >> 6, c = idx & 63;
            d_L2[(size_t)(J + r) * Nn + I + c] = Ts[r][c];
        }
    }
}

// ---------------- Ht[e,:] with w computed inline ----------------
__global__ void k_buildHt(const float* __restrict__ a) {
    int e = blockIdx.x;
    int h = d_heads[e], tt = d_tails[e];
    float a1 = a[1], a2 = a[2], a3 = a[3];
    float V0 = d_u[0][h] - d_u[0][tt];
    float V1 = d_u[1][h] - d_u[1][tt];
    float V2 = d_u[2][h] - d_u[2][tt];
    float w0 = a1 * V0 + a2 * V1 + a3 * V2;
    float w1 = a2 * V0 + a3 * V1;
    float w2 = a3 * V0;
    const float* Lh  = &d_L [(size_t)h  * Nn];
    const float* Lt  = &d_L [(size_t)tt * Nn];
    const float* L2h = &d_L2[(size_t)h  * Nn];
    const float* L2t = &d_L2[(size_t)tt * Nn];
    float* out = &d_Ht[(size_t)e * Nn];
    for (int n = threadIdx.x; n < Nn; n += 256) {
        float v = w1 * (Lh[n] - Lt[n]) + w2 * (L2h[n] - L2t[n]);
        if (n == h)  v += w0;
        if (n == tt) v -= w0;
        out[n] = v;
    }
}

// ---------------- S = H diag(sigma) H^T + C_w  (lower tiles only; prefetched) ----------------
__global__ void k_gemmS(const float* __restrict__ Cw) {
    if (blockIdx.y < blockIdx.x) return;
    __shared__ float As[16][64], Bs[16][64];
    int I = blockIdx.y * 64, J = blockIdx.x * 64;
    int t = threadIdx.x;
    int ldk = t >> 4, ldm = (t & 15) << 2;
    int ty = t >> 4, tx = t & 15;
    float acc[4][4] = {};
    {
        float sg = d_sigma[ldk];
        const float* row = &d_Ht[(size_t)ldk * Nn];
        float4 av = *(const float4*)&row[I + ldm];
        float4 bv = *(const float4*)&row[J + ldm];
        av.x *= sg; av.y *= sg; av.z *= sg; av.w *= sg;
        *(float4*)&As[ldk][ldm] = av;
        *(float4*)&Bs[ldk][ldm] = bv;
    }
    for (int e0 = 0; e0 < Ee; e0 += 16) {
        __syncthreads();
        bool has = (e0 + 16 < Ee);
        float4 an, bn; float sgn = 0.f;
        if (has) {
            sgn = d_sigma[e0 + 16 + ldk];
            const float* row = &d_Ht[(size_t)(e0 + 16 + ldk) * Nn];
            an = *(const float4*)&row[I + ldm];
            bn = *(const float4*)&row[J + ldm];
        }
#pragma unroll
        for (int kk = 0; kk < 16; kk++) {
            float4 a4 = *(const float4*)&As[kk][ty * 4];
            float4 b4 = *(const float4*)&Bs[kk][tx * 4];
            float ar[4] = {a4.x, a4.y, a4.z, a4.w};
            float br[4] = {b4.x, b4.y, b4.z, b4.w};
#pragma unroll
            for (int i = 0; i < 4; i++)
#pragma unroll
                for (int j = 0; j < 4; j++) acc[i][j] += ar[i] * br[j];
        }
        __syncthreads();
        if (has) {
            an.x *= sgn; an.y *= sgn; an.z *= sgn; an.w *= sgn;
            *(float4*)&As[ldk][ldm] = an;
            *(float4*)&Bs[ldk][ldm] = bn;
        }
    }
#pragma unroll
    for (int i = 0; i < 4; i++)
#pragma unroll
        for (int j = 0; j < 4; j++) {
            size_t idx = (size_t)(I + ty * 4 + i) * Nn + J + tx * 4 + j;
            d_S[idx] = acc[i][j] + Cw[idx];
        }
}

// ================= persistent Cholesky + solve + output =================

// 64x64 Cholesky + triangular inverse, ONE sync per pivot (raw-column scheme).
__device__ void potrf_dev(int kblk, float (*A)[NB + 1], float (*Bi)[NB + 1]) {
    __shared__ float dv[NB];
    int o = kblk * NB, t = threadIdx.x;
    __syncthreads();
    for (int idx = t; idx < NB * NB; idx += 256) {
        int r = idx >> 6, c = idx & 63;
        A[r][c] = d_S[(size_t)(o + r) * Nn + o + c];
        Bi[r][c] = (r == c) ? 1.f : 0.f;
    }
    __syncthreads();
    for (int k = 0; k < NB - 1; k++) {
        float dk = A[k][k];            // raw pivot (finalized in pass k-1)
        float invd = 1.f / dk;
        if (t == 0) dv[k] = dk;
        // strip rows r>k; columns untouched-by-this-pass guarantee no hazards:
        //   c<=k : inverse update (reads row k of Bi, col k of A — neither written here)
        //   k<c<=r : factor update (reads col k of A — not written here)
        for (int idx = (k + 1) * NB + t; idx < NB * NB; idx += 256) {
            int r = idx >> 6, c = idx & 63;
            float lrk = A[r][k] * invd;
            if (c <= k)          Bi[r][c] -= lrk * Bi[k][c];
            else if (c <= r)     A[r][c]  -= lrk * A[c][k];
        }
        __syncthreads();
    }
    if (t == 0) dv[NB - 1] = A[NB - 1][NB - 1];
    __syncthreads();
    // final scaling: L[r][c] = A[r][c]/sqrt(d_c); Linv row r scaled by 1/sqrt(d_r)
    for (int idx = t; idx < NB * NB; idx += 256) {
        int r = idx >> 6, c = idx & 63;
        float av;
        if (r > c)       av = A[r][c] * rsqrtf(dv[c]);
        else if (r == c) av = sqrtf(dv[r]);
        else             av = 0.f;
        d_S[(size_t)(o + r) * Nn + o + c] = av;
        float bv = (c <= r) ? Bi[r][c] * rsqrtf(dv[r]) : 0.f;
        d_Linv[kblk * NB * NB + idx] = bv;
    }
    __syncthreads();
}

__device__ void trsm_dev(int kblk, int panel, float (*At)[NB + 1], float (*Lv)[NB + 1]) {
    int o = kblk * NB, t = threadIdx.x;
    int r0 = o + NB + panel * NB;
    __syncthreads();
    for (int idx = t; idx < NB * NB; idx += 256) {
        int r = idx >> 6, c = idx & 63;
        At[r][c] = d_S[(size_t)(r0 + r) * Nn + o + c];
        Lv[r][c] = d_Linv[kblk * NB * NB + idx];
    }
    __syncthreads();
    int ty = t >> 4, tx = t & 15;
    float acc[4][4] = {};
    for (int m = 0; m < NB; m++) {
        float ar[4], br[4];
#pragma unroll
        for (int i = 0; i < 4; i++) { ar[i] = At[ty * 4 + i][m]; br[i] = Lv[tx * 4 + i][m]; }
#pragma unroll
        for (int i = 0; i < 4; i++)
#pragma unroll
            for (int j = 0; j < 4; j++) acc[i][j] += ar[i] * br[j];
    }
    __syncthreads();
#pragma unroll
    for (int i = 0; i < 4; i++)
#pragma unroll
        for (int j = 0; j < 4; j++) {
            d_S[(size_t)(r0 + ty * 4 + i) * Nn + o + tx * 4 + j] = acc[i][j];
            Lv[tx * 4 + j][ty * 4 + i] = acc[i][j];   // transpose for d_U
        }
    __syncthreads();
    for (int idx = t; idx < NB * NB; idx += 256) {
        int r = idx >> 6, c = idx & 63;
        d_U[(size_t)(o + r) * Nn + r0 + c] = Lv[r][c];
    }
    __syncthreads();
}

__device__ void syrk_dev(int kblk, int bi, int bj, float (*Pi)[NB + 1], float (*Pj)[NB + 1]) {
    int o = kblk * NB, t = threadIdx.x;
    int ri = o + NB + bi * NB, rj = o + NB + bj * NB;
    __syncthreads();
    for (int idx = t; idx < NB * NB; idx += 256) {
        int r = idx >> 6, c = idx & 63;
        Pi[r][c] = d_S[(size_t)(ri + r) * Nn + o + c];
        Pj[r][c] = d_S[(size_t)(rj + r) * Nn + o + c];
    }
    __syncthreads();
    int ty = t >> 4, tx = t & 15;
    float acc[4][4] = {};
    for (int m = 0; m < NB; m++) {
        float ar[4], br[4];
#pragma unroll
        for (int i = 0; i < 4; i++) { ar[i] = Pi[ty * 4 + i][m]; br[i] = Pj[tx * 4 + i][m]; }
#pragma unroll
        for (int i = 0; i < 4; i++)
#pragma unroll
            for (int j = 0; j < 4; j++) acc[i][j] += ar[i] * br[j];
    }
    __syncthreads();
#pragma unroll
    for (int i = 0; i < 4; i++)
#pragma unroll
        for (int j = 0; j < 4; j++) {
            size_t idx = (size_t)(ri + ty * 4 + i) * Nn + rj + tx * 4 + j;
            d_S[idx] -= acc[i][j];
        }
    __syncthreads();
}

// forward + backward triangular solves by ONE block (256 threads)
__device__ void solve_dev(float* sh, float (*shB)[NB + 1]) {
    int t = threadIdx.x;
    int r = t >> 2, q = t & 3;
    float* yv   = sh;
    float* zz   = sh + 1024;
    float* part = sh + 2048;
    float* tvv  = sh + 2112;
    for (int k = 0; k < NKB; k++) {
        int o = k * NB;
        float acc = 0.f;
        const float* Srow = &d_S[(size_t)(o + r) * Nn + q * 16];
        for (int cb = 0; cb < k; cb++) {
#pragma unroll
            for (int m = 0; m < 4; m++) {
                float4 v = *(const float4*)&Srow[cb * 64 + m * 4];
                int j = cb * 64 + q * 16 + m * 4;
                acc += v.x * yv[j] + v.y * yv[j + 1] + v.z * yv[j + 2] + v.w * yv[j + 3];
            }
        }
        acc += __shfl_xor_sync(0xffffffffu, acc, 1);
        acc += __shfl_xor_sync(0xffffffffu, acc, 2);
        if (q == 0) part[r] = acc;
        for (int idx = t; idx < NB * NB; idx += 256)
            shB[idx >> 6][idx & 63] = d_Linv[k * NB * NB + idx];
        __syncthreads();
        if (t < NB) tvv[t] = d_r[o + t] - part[t];
        __syncthreads();
        if (t < NB) {
            float a2 = 0.f;
#pragma unroll
            for (int m = 0; m < NB; m++) a2 += shB[t][m] * tvv[m];
            yv[o + t] = a2;
        }
        __syncthreads();
    }
    for (int k = NKB - 1; k >= 0; k--) {
        int o = k * NB;
        float acc = 0.f;
        const float* Urow = &d_U[(size_t)(o + r) * Nn + q * 16];
        for (int rb = k + 1; rb < NKB; rb++) {
#pragma unroll
            for (int m = 0; m < 4; m++) {
                float4 v = *(const float4*)&Urow[rb * 64 + m * 4];
                int j = rb * 64 + q * 16 + m * 4;
                acc += v.x * zz[j] + v.y * zz[j + 1] + v.z * zz[j + 2] + v.w * zz[j + 3];
            }
        }
        acc += __shfl_xor_sync(0xffffffffu, acc, 1);
        acc += __shfl_xor_sync(0xffffffffu, acc, 2);
        if (q == 0) part[r] = acc;
        for (int idx = t; idx < NB * NB; idx += 256)
            shB[idx >> 6][idx & 63] = d_Linv[k * NB * NB + idx];
        __syncthreads();
        if (t < NB) tvv[t] = yv[o + t] - part[t];
        __syncthreads();
        if (t < NB) {
            float a2 = 0.f;
#pragma unroll
            for (int m = 0; m < NB; m++) a2 += shB[m][t] * tvv[m];
            zz[o + t] = a2;
        }
        __syncthreads();
    }
    for (int n = t; n < Nn; n += 256) d_z[n] = zz[n];
}

__device__ void matvec_dev(const float* src, float* dst, int bid, int t, float* ws) {
    for (int row = bid; row < Nn; row += GPB) {
        float4 lv = *(const float4*)&d_L[(size_t)row * Nn + t * 4];
        float4 zv = *(const float4*)&src[t * 4];
        float acc = lv.x * zv.x + lv.y * zv.y + lv.z * zv.z + lv.w * zv.w;
        for (int off = 16; off; off >>= 1) acc += __shfl_down_sync(0xffffffffu, acc, off);
        if ((t & 31) == 0) ws[t >> 5] = acc;
        __syncthreads();
        if (t == 0) {
            float s = 0.f;
#pragma unroll
            for (int w = 0; w < 8; w++) s += ws[w];
            dst[row] = s;
        }
        __syncthreads();
    }
}

__global__ void __launch_bounds__(256, 1)
k_chol_all(const float* __restrict__ a, const float* __restrict__ y, float* __restrict__ out) {
    __shared__ float shA[NB][NB + 1];
    __shared__ float shB[NB][NB + 1];
    __shared__ float ws[8];
    int bid = blockIdx.x, t = threadIdx.x;
    unsigned gen = 0;

    // phase 0
    if (bid == 0) {
        potrf_dev(0, shA, shB);
    } else if (bid == GPB - 1) {
        if (t == 0) { g_gen_dev[0] = 0u; g_cnt_dev[0] = 0u; }   // reset front barrier for next replay
        float a0 = a[0], a1 = a[1], a2 = a[2], a3 = a[3];
        for (int n = t; n < Nn; n += 256)
            d_r[n] = y[n] - (a0 * d_u[0][n] + a1 * d_u[1][n] + a2 * d_u[2][n] + a3 * d_u[3][n]);
    }
    gridbar(1, ++gen);

    for (int k = 0; k < NKB - 1; k++) {
        int rb = NKB - 1 - k;
        if (bid < rb) trsm_dev(k, bid, shA, shB);
        gridbar(1, ++gen);
        int T = rb * (rb + 1) / 2;
        if (bid == 0) {
            syrk_dev(k, 0, 0, shA, shB);
            potrf_dev(k + 1, shA, shB);                  // lookahead: only this block
        } else {
            for (int tt = bid; tt < T; tt += GPB - 1) {  // blocks 1..119 cover tiles 1..T-1
                int bi = (int)((sqrtf(8.f * tt + 1.f) - 1.f) * 0.5f);
                while ((bi + 1) * (bi + 2) / 2 <= tt) bi++;
                while (bi * (bi + 1) / 2 > tt) bi--;
                int bj = tt - bi * (bi + 1) / 2;
                syrk_dev(k, bi, bj, shA, shB);
            }
        }
        gridbar(1, ++gen);
    }

    if (bid == 0) solve_dev(&shA[0][0], shB);
    gridbar(1, ++gen);
    matvec_dev(d_z,  d_v1, bid, t, ws);     // v1 = L z
    gridbar(1, ++gen);
    matvec_dev(d_v1, d_v2, bid, t, ws);     // v2 = L^2 z
    gridbar(1, ++gen);

    // out[e] = relu(s + sigma * (w0*(z_h-z_t) + w1*(v1_h-v1_t) + w2*(v2_h-v2_t)))
    float a1 = a[1], a2 = a[2], a3 = a[3];
    for (int e = bid * 256 + t; e < Ee; e += GPB * 256) {
        int h = d_heads[e], tl = d_tails[e];
        float V0 = d_u[0][h] - d_u[0][tl];
        float V1 = d_u[1][h] - d_u[1][tl];
        float V2 = d_u[2][h] - d_u[2][tl];
        float w0 = a1 * V0 + a2 * V1 + a3 * V2;
        float w1 = a2 * V0 + a3 * V1;
        float w2 = a3 * V0;
        float dotv = w0 * (d_z[h] - d_z[tl]) + w1 * (d_v1[h] - d_v1[tl]) + w2 * (d_v2[h] - d_v2[tl]);
        out[e] = fmaxf(d_s[e] + d_sigma[e] * dotv, 0.f);
    }
}

// ---------------- launch ----------------
extern "C" void kernel_launch(void* const* d_in, const int* in_sizes, int n_in,
                              void* d_out, int out_size) {
    (void)in_sizes; (void)n_in; (void)out_size;
    const float* F  = (const float*)d_in[0];
    const float* B  = (const float*)d_in[1];
    const float* Cu = (const float*)d_in[2];
    const float* Cw = (const float*)d_in[3];
    const float* Cx = (const float*)d_in[4];
    const float* s0 = (const float*)d_in[5];
    const float* a  = (const float*)d_in[6];
    const float* q  = (const float*)d_in[7];
    const float* y  = (const float*)d_in[8];
    float* out = (float*)d_out;

    k_front<<<GPB, 256>>>(B, F, Cu, Cx, s0, q);     // #1
    k_gemmL2<<<dim3(16, 16), 256>>>();              // #2
    k_buildHt<<<Ee, 256>>>(a);                      // #3
    k_gemmS<<<dim3(16, 16), 256>>>(Cw);             // #4  <- ncu capture slot
    k_chol_all<<<GPB, 256>>>(a, y, out);            // #5
}

// round 6
// speedup vs baseline: 1.3412x; 1.1672x over previous
#include <cuda_runtime.h>
#include <math.h>

#define Nn 1024
#define Ee 4096
#define NB 64
#define NKB 16   // Nn / NB
#define GPB 136  // persistent grid blocks (1 per SM, all co-resident)

// ---------------- scratch (static device globals; no allocation) ----------------
__device__ int   d_heads[Ee], d_tails[Ee];
__device__ float d_s[Ee], d_sigma[Ee];
__device__ float d_u[4][Nn];
__device__ float d_r[Nn], d_z[Nn], d_v1[Nn], d_v2[Nn];
__device__ float d_L [Nn * Nn];
__device__ float d_L2[Nn * Nn];        // L^2; reused as Lfac (factor panels) inside chol
__device__ float d_S [Nn * Nn];
__device__ float d_U [Nn * Nn];        // transposed factor panels (backward solve)
__device__ float d_Ht[(size_t)Ee * Nn];
__device__ float d_Linv[NKB * NB * NB];
__device__ unsigned g_gen_dev[4];      // 0: front, 1: chol main, 2: HtS, 3: chol trsm-color
__device__ unsigned g_cnt_dev[4];

#define d_Lfac d_L2

// ================= grid barrier (spin), parametric participant count =================
__device__ __forceinline__ void gridbar(int which, unsigned target, unsigned count) {
    __syncthreads();
    if (threadIdx.x == 0) {
        __threadfence();
        unsigned v = atomicAdd(&g_cnt_dev[which], 1u);
        if (v == count - 1) {
            atomicExch(&g_cnt_dev[which], 0u);
            __threadfence();
            atomicExch(&g_gen_dev[which], target);
        } else {
            while (*(volatile unsigned*)&g_gen_dev[which] < target) { }
        }
        __threadfence();
    }
    __syncthreads();
}

// ---------------- persistent front: extract + init + assemble + 3 matvecs ----------------
__global__ void __launch_bounds__(256, 1)
k_front(const float* __restrict__ B, const float* __restrict__ F,
        const float* __restrict__ Cu, const float* __restrict__ Cx,
        const float* __restrict__ s0, const float* __restrict__ q) {
    int bid = blockIdx.x, t = threadIdx.x;
    __shared__ float ws[8];
    unsigned gen = 0;
    if (bid == 0 && t == 0) { g_gen_dev[2] = 0u; g_cnt_dev[2] = 0u; }  // reset HtS barrier
    // phase A: extract incidence, zero L, diag setup, copy q
    for (int idx = bid * 256 + t; idx < Nn * Ee; idx += GPB * 256) {
        float v = B[idx];
        int e = idx & (Ee - 1), n = idx >> 12;
        if (v > 0.5f)       d_heads[e] = n;
        else if (v < -0.5f) d_tails[e] = n;
        if (idx < Nn * Nn) d_L[idx] = 0.f;
        if (idx < Ee) {
            size_t d = (size_t)idx * Ee + idx;
            float f = F[d];
            d_s[idx] = f * s0[idx];
            d_sigma[idx] = f * f * Cx[d] + Cu[d];
        }
        if (idx < Nn) d_u[0][idx] = q[idx];
    }
    gridbar(0, ++gen, GPB);
    // phase B: assemble Laplacian
    for (int e = bid * 256 + t; e < Ee; e += GPB * 256) {
        float se = d_s[e];
        int h = d_heads[e], tl = d_tails[e];
        atomicAdd(&d_L[h * Nn + h],  se);
        atomicAdd(&d_L[tl * Nn + tl],  se);
        atomicAdd(&d_L[h * Nn + tl], -se);
        atomicAdd(&d_L[tl * Nn + h], -se);
    }
    gridbar(0, ++gen, GPB);
    // phase C: u_{m+1} = L u_m, three times
    for (int m = 0; m < 3; m++) {
        for (int row = bid; row < Nn; row += GPB) {
            float4 lv = *(const float4*)&d_L[(size_t)row * Nn + t * 4];
            float4 uv = *(const float4*)&d_u[m][t * 4];
            float acc = lv.x * uv.x + lv.y * uv.y + lv.z * uv.z + lv.w * uv.w;
            for (int off = 16; off; off >>= 1) acc += __shfl_down_sync(0xffffffffu, acc, off);
            if ((t & 31) == 0) ws[t >> 5] = acc;
            __syncthreads();
            if (t == 0) {
                float s = 0.f;
#pragma unroll
                for (int w = 0; w < 8; w++) s += ws[w];
                d_u[m + 1][row] = s;
            }
            __syncthreads();
        }
        gridbar(0, ++gen, GPB);
    }
}

// ---------------- L2 = L * L^T (symmetric; compute lower, mirror; prefetched) ----------------
__global__ void k_gemmL2() {
    if (blockIdx.x == 0 && blockIdx.y == 0 && threadIdx.x == 0) {
        g_gen_dev[1] = 0u; g_cnt_dev[1] = 0u;   // reset chol barriers for this replay
        g_gen_dev[3] = 0u; g_cnt_dev[3] = 0u;
    }
    if (blockIdx.y < blockIdx.x) return;
    __shared__ float As[16][65], Bs[16][65];
    __shared__ float Ts[64][65];
    int I = blockIdx.y * 64, J = blockIdx.x * 64;
    int t = threadIdx.x;
    int lm = t >> 2, lk = (t & 3) << 2;
    int ty = t >> 4, tx = t & 15;
    float acc[4][4] = {};
    float4 av = *(const float4*)&d_L[(size_t)(I + lm) * Nn + lk];
    float4 bv = *(const float4*)&d_L[(size_t)(J + lm) * Nn + lk];
    As[lk + 0][lm] = av.x; As[lk + 1][lm] = av.y; As[lk + 2][lm] = av.z; As[lk + 3][lm] = av.w;
    Bs[lk + 0][lm] = bv.x; Bs[lk + 1][lm] = bv.y; Bs[lk + 2][lm] = bv.z; Bs[lk + 3][lm] = bv.w;
    for (int k0 = 0; k0 < Nn; k0 += 16) {
        __syncthreads();
        bool has = (k0 + 16 < Nn);
        float4 an, bn;
        if (has) {
            an = *(const float4*)&d_L[(size_t)(I + lm) * Nn + k0 + 16 + lk];
            bn = *(const float4*)&d_L[(size_t)(J + lm) * Nn + k0 + 16 + lk];
        }
#pragma unroll
        for (int kk = 0; kk < 16; kk++) {
            float ar[4], br[4];
#pragma unroll
            for (int i = 0; i < 4; i++) { ar[i] = As[kk][ty * 4 + i]; br[i] = Bs[kk][tx * 4 + i]; }
#pragma unroll
            for (int i = 0; i < 4; i++)
#pragma unroll
                for (int j = 0; j < 4; j++) acc[i][j] += ar[i] * br[j];
        }
        __syncthreads();
        if (has) {
            As[lk + 0][lm] = an.x; As[lk + 1][lm] = an.y; As[lk + 2][lm] = an.z; As[lk + 3][lm] = an.w;
            Bs[lk + 0][lm] = bn.x; Bs[lk + 1][lm] = bn.y; Bs[lk + 2][lm] = bn.z; Bs[lk + 3][lm] = bn.w;
        }
    }
#pragma unroll
    for (int i = 0; i < 4; i++)
#pragma unroll
        for (int j = 0; j < 4; j++)
            d_L2[(size_t)(I + ty * 4 + i) * Nn + J + tx * 4 + j] = acc[i][j];
    if (blockIdx.y != blockIdx.x) {
#pragma unroll
        for (int i = 0; i < 4; i++)
#pragma unroll
            for (int j = 0; j < 4; j++)
                Ts[tx * 4 + j][ty * 4 + i] = acc[i][j];
        __syncthreads();
        for (int idx = t; idx < 64 * 64; idx += 256) {
            int r = idx >> 6, c = idx & 63;
            d_L2[(size_t)(J + r) * Nn + I + c] = Ts[r][c];
        }
    }
}

// ---------------- fused buildHt + gemmS (persistent, GPB blocks) ----------------
__device__ void gemmS_tile(int I, int J, const float* __restrict__ Cw) {
    __shared__ float As[16][64], Bs[16][64];
    int t = threadIdx.x;
    int ldk = t >> 4, ldm = (t & 15) << 2;
    int ty = t >> 4, tx = t & 15;
    float acc[4][4] = {};
    __syncthreads();
    {
        float sg = d_sigma[ldk];
        const float* row = &d_Ht[(size_t)ldk * Nn];
        float4 av = *(const float4*)&row[I + ldm];
        float4 bv = *(const float4*)&row[J + ldm];
        av.x *= sg; av.y *= sg; av.z *= sg; av.w *= sg;
        *(float4*)&As[ldk][ldm] = av;
        *(float4*)&Bs[ldk][ldm] = bv;
    }
    for (int e0 = 0; e0 < Ee; e0 += 16) {
        __syncthreads();
        bool has = (e0 + 16 < Ee);
        float4 an, bn; float sgn = 0.f;
        if (has) {
            sgn = d_sigma[e0 + 16 + ldk];
            const float* row = &d_Ht[(size_t)(e0 + 16 + ldk) * Nn];
            an = *(const float4*)&row[I + ldm];
            bn = *(const float4*)&row[J + ldm];
        }
#pragma unroll
        for (int kk = 0; kk < 16; kk++) {
            float4 a4 = *(const float4*)&As[kk][ty * 4];
            float4 b4 = *(const float4*)&Bs[kk][tx * 4];
            float ar[4] = {a4.x, a4.y, a4.z, a4.w};
            float br[4] = {b4.x, b4.y, b4.z, b4.w};
#pragma unroll
            for (int i = 0; i < 4; i++)
#pragma unroll
                for (int j = 0; j < 4; j++) acc[i][j] += ar[i] * br[j];
        }
        __syncthreads();
        if (has) {
            an.x *= sgn; an.y *= sgn; an.z *= sgn; an.w *= sgn;
            *(float4*)&As[ldk][ldm] = an;
            *(float4*)&Bs[ldk][ldm] = bn;
        }
    }
#pragma unroll
    for (int i = 0; i < 4; i++)
#pragma unroll
        for (int j = 0; j < 4; j++) {
            size_t idx = (size_t)(I + ty * 4 + i) * Nn + J + tx * 4 + j;
            d_S[idx] = acc[i][j] + Cw[idx];
        }
    __syncthreads();
}

__global__ void __launch_bounds__(256, 1)
k_HtS(const float* __restrict__ a, const float* __restrict__ Cw) {
    int bid = blockIdx.x, t = threadIdx.x;
    float a1 = a[1], a2 = a[2], a3 = a[3];
    // phase 1: build Ht rows (one edge per block-iteration; thread t = float4 chunk)
    for (int e = bid; e < Ee; e += GPB) {
        int h = d_heads[e], tt = d_tails[e];
        float V0 = d_u[0][h] - d_u[0][tt];
        float V1 = d_u[1][h] - d_u[1][tt];
        float V2 = d_u[2][h] - d_u[2][tt];
        float w0 = a1 * V0 + a2 * V1 + a3 * V2;
        float w1 = a2 * V0 + a3 * V1;
        float w2 = a3 * V0;
        float4 lh = *(const float4*)&d_L [(size_t)h  * Nn + t * 4];
        float4 lt = *(const float4*)&d_L [(size_t)tt * Nn + t * 4];
        float4 qh = *(const float4*)&d_L2[(size_t)h  * Nn + t * 4];
        float4 qt = *(const float4*)&d_L2[(size_t)tt * Nn + t * 4];
        float4 v;
        v.x = w1 * (lh.x - lt.x) + w2 * (qh.x - qt.x);
        v.y = w1 * (lh.y - lt.y) + w2 * (qh.y - qt.y);
        v.z = w1 * (lh.z - lt.z) + w2 * (qh.z - qt.z);
        v.w = w1 * (lh.w - lt.w) + w2 * (qh.w - qt.w);
        int n0 = t * 4;
        float* vp = (float*)&v;
        if (h  >= n0 && h  < n0 + 4) vp[h  - n0] += w0;
        if (tt >= n0 && tt < n0 + 4) vp[tt - n0] -= w0;
        *(float4*)&d_Ht[(size_t)e * Nn + n0] = v;
    }
    gridbar(2, 1, GPB);
    // phase 2: S lower tiles, exactly one per block (136 tiles, 136 blocks)
    for (int item = bid; item < 136; item += GPB) {
        int bi = (int)((sqrtf(8.f * item + 1.f) - 1.f) * 0.5f);
        while ((bi + 1) * (bi + 2) / 2 <= item) bi++;
        while (bi * (bi + 1) / 2 > item) bi--;
        int bj = item - bi * (bi + 1) / 2;
        gemmS_tile(bi * 64, bj * 64, Cw);
    }
}

// ================= persistent Cholesky + solve + output =================

// potrf core: A (raw tile) + Bi (identity) in smem; writes d_Linv ONLY.
__device__ void potrf_core(int kblk, float (*A)[NB + 1], float (*Bi)[NB + 1]) {
    __shared__ float dv[NB];
    int t = threadIdx.x;
    __syncthreads();
    for (int k = 0; k < NB - 1; k++) {
        float dk = A[k][k];
        float invd = 1.f / dk;
        if (t == 0) dv[k] = dk;
        for (int idx = (k + 1) * NB + t; idx < NB * NB; idx += 256) {
            int r = idx >> 6, c = idx & 63;
            float lrk = A[r][k] * invd;
            if (c <= k)          Bi[r][c] -= lrk * Bi[k][c];
            else if (c <= r)     A[r][c]  -= lrk * A[c][k];
        }
        __syncthreads();
    }
    if (t == 0) dv[NB - 1] = A[NB - 1][NB - 1];
    __syncthreads();
    for (int idx = t; idx < NB * NB; idx += 256) {
        int r = idx >> 6, c = idx & 63;
        float bv = (c <= r) ? Bi[r][c] * rsqrtf(dv[r]) : 0.f;
        d_Linv[kblk * NB * NB + idx] = bv;
    }
    __syncthreads();
}

__device__ void potrf_from_global(int kblk, float (*A)[NB + 1], float (*Bi)[NB + 1]) {
    int o = kblk * NB, t = threadIdx.x;
    __syncthreads();
    for (int idx = t; idx < NB * NB; idx += 256) {
        int r = idx >> 6, c = idx & 63;
        A[r][c] = d_S[(size_t)(o + r) * Nn + o + c];
        Bi[r][c] = (r == c) ? 1.f : 0.f;
    }
    potrf_core(kblk, A, Bi);
}

// trsm: input from d_S (pristine), result left in At; if store, write d_Lfac + d_U
__device__ void trsm_dev(int kblk, int panel, float (*At)[NB + 1], float (*Lv)[NB + 1], bool store) {
    int o = kblk * NB, t = threadIdx.x;
    int r0 = o + NB + panel * NB;
    __syncthreads();
    for (int idx = t; idx < NB * NB; idx += 256) {
        int r = idx >> 6, c = idx & 63;
        At[r][c] = d_S[(size_t)(r0 + r) * Nn + o + c];
        Lv[r][c] = d_Linv[kblk * NB * NB + idx];
    }
    __syncthreads();
    int ty = t >> 4, tx = t & 15;
    float acc[4][4] = {};
    for (int m = 0; m < NB; m++) {
        float ar[4], br[4];
#pragma unroll
        for (int i = 0; i < 4; i++) { ar[i] = At[ty * 4 + i][m]; br[i] = Lv[tx * 4 + i][m]; }
#pragma unroll
        for (int i = 0; i < 4; i++)
#pragma unroll
            for (int j = 0; j < 4; j++) acc[i][j] += ar[i] * br[j];
    }
    __syncthreads();
#pragma unroll
    for (int i = 0; i < 4; i++)
#pragma unroll
        for (int j = 0; j < 4; j++) {
            At[ty * 4 + i][tx * 4 + j] = acc[i][j];
            if (store) Lv[tx * 4 + j][ty * 4 + i] = acc[i][j];
        }
    __syncthreads();
    if (store) {
        for (int idx = t; idx < NB * NB; idx += 256) {
            int r = idx >> 6, c = idx & 63;
            d_Lfac[(size_t)(r0 + r) * Nn + o + c] = At[r][c];
            d_U[(size_t)(o + r) * Nn + r0 + c]   = Lv[r][c];
        }
        __syncthreads();
    }
}

// trailing update: d_S(tile) -= P_bi P_bj^T, panels read from d_Lfac
__device__ void syrk_dev(int kblk, int bi, int bj, float (*Pi)[NB + 1], float (*Pj)[NB + 1]) {
    int o = kblk * NB, t = threadIdx.x;
    int ri = o + NB + bi * NB, rj = o + NB + bj * NB;
    __syncthreads();
    for (int idx = t; idx < NB * NB; idx += 256) {
        int r = idx >> 6, c = idx & 63;
        Pi[r][c] = d_Lfac[(size_t)(ri + r) * Nn + o + c];
        Pj[r][c] = d_Lfac[(size_t)(rj + r) * Nn + o + c];
    }
    __syncthreads();
    int ty = t >> 4, tx = t & 15;
    float acc[4][4] = {};
    for (int m = 0; m < NB; m++) {
        float ar[4], br[4];
#pragma unroll
        for (int i = 0; i < 4; i++) { ar[i] = Pi[ty * 4 + i][m]; br[i] = Pj[tx * 4 + i][m]; }
#pragma unroll
        for (int i = 0; i < 4; i++)
#pragma unroll
            for (int j = 0; j < 4; j++) acc[i][j] += ar[i] * br[j];
    }
    __syncthreads();
#pragma unroll
    for (int i = 0; i < 4; i++)
#pragma unroll
        for (int j = 0; j < 4; j++) {
            size_t idx = (size_t)(ri + ty * 4 + i) * Nn + rj + tx * 4 + j;
            d_S[idx] -= acc[i][j];
        }
    __syncthreads();
}

// block 0's lookahead chain: private trsm(panel0) -> syrk(0,0) in smem -> potrf(k+1)
__device__ void block0_chain(int k, float (*shA)[NB + 1], float (*shB)[NB + 1]) {
    int t = threadIdx.x;
    trsm_dev(k, 0, shA, shB, false);              // result P in shA
    int ty = t >> 4, tx = t & 15;
    float acc[4][4] = {};
    for (int m = 0; m < NB; m++) {
        float ar[4], br[4];
#pragma unroll
        for (int i = 0; i < 4; i++) { ar[i] = shA[ty * 4 + i][m]; br[i] = shA[tx * 4 + i][m]; }
#pragma unroll
        for (int i = 0; i < 4; i++)
#pragma unroll
            for (int j = 0; j < 4; j++) acc[i][j] += ar[i] * br[j];
    }
    __syncthreads();
    int o2 = (k + 1) * NB;
#pragma unroll
    for (int i = 0; i < 4; i++)
#pragma unroll
        for (int j = 0; j < 4; j++)
            shB[ty * 4 + i][tx * 4 + j] =
                d_S[(size_t)(o2 + ty * 4 + i) * Nn + o2 + tx * 4 + j] - acc[i][j];
    __syncthreads();
    for (int idx = t; idx < NB * NB; idx += 256) {
        int r = idx >> 6, c = idx & 63;
        shA[r][c] = (r == c) ? 1.f : 0.f;
    }
    potrf_core(k + 1, shB, shA);
}

// forward + backward triangular solves by ONE block (256 threads)
__device__ void solve_dev(float* sh, float (*shB)[NB + 1]) {
    int t = threadIdx.x;
    int r = t >> 2, q = t & 3;
    float* yv   = sh;
    float* zz   = sh + 1024;
    float* part = sh + 2048;
    float* tvv  = sh + 2112;
    for (int k = 0; k < NKB; k++) {
        int o = k * NB;
        float acc = 0.f;
        const float* Srow = &d_Lfac[(size_t)(o + r) * Nn + q * 16];
        for (int cb = 0; cb < k; cb++) {
#pragma unroll
            for (int m = 0; m < 4; m++) {
                float4 v = *(const float4*)&Srow[cb * 64 + m * 4];
                int j = cb * 64 + q * 16 + m * 4;
                acc += v.x * yv[j] + v.y * yv[j + 1] + v.z * yv[j + 2] + v.w * yv[j + 3];
            }
        }
        acc += __shfl_xor_sync(0xffffffffu, acc, 1);
        acc += __shfl_xor_sync(0xffffffffu, acc, 2);
        if (q == 0) part[r] = acc;
        for (int idx = t; idx < NB * NB; idx += 256)
            shB[idx >> 6][idx & 63] = d_Linv[k * NB * NB + idx];
        __syncthreads();
        if (t < NB) tvv[t] = d_r[o + t] - part[t];
        __syncthreads();
        if (t < NB) {
            float a2 = 0.f;
#pragma unroll
            for (int m = 0; m < NB; m++) a2 += shB[t][m] * tvv[m];
            yv[o + t] = a2;
        }
        __syncthreads();
    }
    for (int k = NKB - 1; k >= 0; k--) {
        int o = k * NB;
        float acc = 0.f;
        const float* Urow = &d_U[(size_t)(o + r) * Nn + q * 16];
        for (int rb = k + 1; rb < NKB; rb++) {
#pragma unroll
            for (int m = 0; m < 4; m++) {
                float4 v = *(const float4*)&Urow[rb * 64 + m * 4];
                int j = rb * 64 + q * 16 + m * 4;
                acc += v.x * zz[j] + v.y * zz[j + 1] + v.z * zz[j + 2] + v.w * zz[j + 3];
            }
        }
        acc += __shfl_xor_sync(0xffffffffu, acc, 1);
        acc += __shfl_xor_sync(0xffffffffu, acc, 2);
        if (q == 0) part[r] = acc;
        for (int idx = t; idx < NB * NB; idx += 256)
            shB[idx >> 6][idx & 63] = d_Linv[k * NB * NB + idx];
        __syncthreads();
        if (t < NB) tvv[t] = yv[o + t] - part[t];
        __syncthreads();
        if (t < NB) {
            float a2 = 0.f;
#pragma unroll
            for (int m = 0; m < NB; m++) a2 += shB[m][t] * tvv[m];
            zz[o + t] = a2;
        }
        __syncthreads();
    }
    for (int n = t; n < Nn; n += 256) d_z[n] = zz[n];
}

__device__ void matvec_dev(const float* src, float* dst, int bid, int t, float* ws) {
    for (int row = bid; row < Nn; row += GPB) {
        float4 lv = *(const float4*)&d_L[(size_t)row * Nn + t * 4];
        float4 zv = *(const float4*)&src[t * 4];
        float acc = lv.x * zv.x + lv.y * zv.y + lv.z * zv.z + lv.w * zv.w;
        for (int off = 16; off; off >>= 1) acc += __shfl_down_sync(0xffffffffu, acc, off);
        if ((t & 31) == 0) ws[t >> 5] = acc;
        __syncthreads();
        if (t == 0) {
            float s = 0.f;
#pragma unroll
            for (int w = 0; w < 8; w++) s += ws[w];
            dst[row] = s;
        }
        __syncthreads();
    }
}

__global__ void __launch_bounds__(256, 1)
k_chol_all(const float* __restrict__ a, const float* __restrict__ y, float* __restrict__ out) {
    __shared__ float shA[NB][NB + 1];
    __shared__ float shB[NB][NB + 1];
    __shared__ float ws[8];
    int bid = blockIdx.x, t = threadIdx.x;
    unsigned genB = 0, genA = 0;

    // phase 0
    if (bid == 0) {
        potrf_from_global(0, shA, shB);
    } else if (bid == GPB - 1) {
        if (t == 0) { g_gen_dev[0] = 0u; g_cnt_dev[0] = 0u; }   // reset front barrier
        float a0 = a[0], a1 = a[1], a2 = a[2], a3 = a[3];
        for (int n = t; n < Nn; n += 256)
            d_r[n] = y[n] - (a0 * d_u[0][n] + a1 * d_u[1][n] + a2 * d_u[2][n] + a3 * d_u[3][n]);
    }
    gridbar(1, ++genB, GPB);

    for (int k = 0; k < NKB - 1; k++) {
        int rb = NKB - 1 - k;
        if (bid == 0) {
            block0_chain(k, shA, shB);    // overlaps others' trsm + syrk phases
        } else {
            if (bid <= rb) trsm_dev(k, bid - 1, shA, shB, true);
            gridbar(3, ++genA, GPB - 1);  // trsm->syrk sync among blocks 1..GPB-1
            int T = rb * (rb + 1) / 2;
            for (int tt = bid; tt < T; tt += GPB - 1) {   // tiles 1..T-1 (tile 0 = block 0's)
                int bi = (int)((sqrtf(8.f * tt + 1.f) - 1.f) * 0.5f);
                while ((bi + 1) * (bi + 2) / 2 <= tt) bi++;
                while (bi * (bi + 1) / 2 > tt) bi--;
                int bj = tt - bi * (bi + 1) / 2;
                syrk_dev(k, bi, bj, shA, shB);
            }
        }
        gridbar(1, ++genB, GPB);
    }

    if (bid == 0) solve_dev(&shA[0][0], shB);
    gridbar(1, ++genB, GPB);
    matvec_dev(d_z,  d_v1, bid, t, ws);
    gridbar(1, ++genB, GPB);
    matvec_dev(d_v1, d_v2, bid, t, ws);
    gridbar(1, ++genB, GPB);

    float a1 = a[1], a2 = a[2], a3 = a[3];
    for (int e = bid * 256 + t; e < Ee; e += GPB * 256) {
        int h = d_heads[e], tl = d_tails[e];
        float V0 = d_u[0][h] - d_u[0][tl];
        float V1 = d_u[1][h] - d_u[1][tl];
        float V2 = d_u[2][h] - d_u[2][tl];
        float w0 = a1 * V0 + a2 * V1 + a3 * V2;
        float w1 = a2 * V0 + a3 * V1;
        float w2 = a3 * V0;
        float dotv = w0 * (d_z[h] - d_z[tl]) + w1 * (d_v1[h] - d_v1[tl]) + w2 * (d_v2[h] - d_v2[tl]);
        out[e] = fmaxf(d_s[e] + d_sigma[e] * dotv, 0.f);
    }
}

// ---------------- launch ----------------
extern "C" void kernel_launch(void* const* d_in, const int* in_sizes, int n_in,
                              void* d_out, int out_size) {
    (void)in_sizes; (void)n_in; (void)out_size;
    const float* F  = (const float*)d_in[0];
    const float* B  = (const float*)d_in[1];
    const float* Cu = (const float*)d_in[2];
    const float* Cw = (const float*)d_in[3];
    const float* Cx = (const float*)d_in[4];
    const float* s0 = (const float*)d_in[5];
    const float* a  = (const float*)d_in[6];
    const float* q  = (const float*)d_in[7];
    const float* y  = (const float*)d_in[8];
    float* out = (float*)d_out;

    k_front<<<GPB, 256>>>(B, F, Cu, Cx, s0, q);     // #1
    k_gemmL2<<<dim3(16, 16), 256>>>();              // #2
    k_HtS<<<GPB, 256>>>(a, Cw);                     // #3
    k_chol_all<<<GPB, 256>>>(a, y, out);            // #4  <- ncu capture slot
}